// round 14
// baseline (speedup 1.0000x reference)
#include <cuda_runtime.h>
#include <cuda_fp16.h>
#include <math.h>
#include <stdint.h>

// SparseMoE: T=2048, D=1024, F=4096, E=8, top-2.
// memset(ctrs,out) -> router -> [gather || convert W1] ->
// MEGA launch: [convert W2 (z=0) || GEMM1 e=z-1 (z=1..8, publishes per-expert
// done counters) || GEMM2 e=z-9 (z=9..16, spins on counters, atomic out)].
// GEMM: 128x128 tile, 256 thr (8 warps, 2x4, 64x32/warp), 3-stage ring,
// 2 CTAs/SM, ks-level B-fragment double buffering.

#define D_DIM 1024
#define E_NUM 8
#define F_DIM 4096
#define MAXT  2048
#define MAXROWS (2 * MAXT)

// -------------------- device scratch (no cudaMalloc allowed) ---------------
__device__ __half g_w1h[(size_t)E_NUM * D_DIM * F_DIM];
__device__ __half g_w2h[(size_t)E_NUM * F_DIM * D_DIM];
__device__ __half g_xh[(size_t)MAXROWS * D_DIM];
__device__ __half g_hh[(size_t)MAXROWS * F_DIM];
__device__ int   g_ctrs[32];   // [0..7] expert counts, [8..15] gemm1 done,
                               // [16] w2 ready
__device__ int   g_topi[MAXT * 2];
__device__ float g_gate[MAXT * 2];
__device__ int   g_pos[MAXT * 2];
__device__ int   g_rowtok[MAXROWS];
__device__ float g_rowgate[MAXROWS];

// -------------------- helpers ----------------------------------------------
__device__ __forceinline__ uint32_t smem_u32(const void* p) {
    uint32_t a;
    asm("{ .reg .u64 t; cvta.to.shared.u64 t, %1; cvt.u32.u64 %0, t; }"
        : "=r"(a) : "l"(p));
    return a;
}

#define SW128(o) ((uint32_t)(o) ^ ((((uint32_t)(o)) >> 3) & 0x70u))

#define CPASYNC16(s, g) \
    asm volatile("cp.async.cg.shared.global [%0], [%1], 16;" \
        :: "r"((uint32_t)(s)), "l"(g) : "memory")
#define CPCOMMIT() asm volatile("cp.async.commit_group;" ::: "memory")
#define CPWAIT1()  asm volatile("cp.async.wait_group 1;" ::: "memory")
#define CPWAIT0()  asm volatile("cp.async.wait_group 0;" ::: "memory")

__device__ __forceinline__ void ldsm_x4(uint32_t* r, uint32_t addr) {
    asm volatile("ldmatrix.sync.aligned.m8n8.x4.shared.b16 {%0,%1,%2,%3}, [%4];"
        : "=r"(r[0]), "=r"(r[1]), "=r"(r[2]), "=r"(r[3]) : "r"(addr));
}
__device__ __forceinline__ void ldsm_x4_t(uint32_t* r, uint32_t addr) {
    asm volatile("ldmatrix.sync.aligned.m8n8.x4.trans.shared.b16 {%0,%1,%2,%3}, [%4];"
        : "=r"(r[0]), "=r"(r[1]), "=r"(r[2]), "=r"(r[3]) : "r"(addr));
}
__device__ __forceinline__ void mma16816(float* c, const uint32_t* a,
                                         uint32_t b0, uint32_t b1) {
    asm volatile(
        "mma.sync.aligned.m16n8k16.row.col.f32.f16.f16.f32 "
        "{%0,%1,%2,%3}, {%4,%5,%6,%7}, {%8,%9}, {%0,%1,%2,%3};"
        : "+f"(c[0]), "+f"(c[1]), "+f"(c[2]), "+f"(c[3])
        : "r"(a[0]), "r"(a[1]), "r"(a[2]), "r"(a[3]), "r"(b0), "r"(b1));
}

__device__ __forceinline__ uint32_t pack2h(float a, float b) {
    __half2 h = __floats2half2_rn(a, b);
    return *(uint32_t*)&h;
}

__device__ __forceinline__ void cvt_u4(const float* __restrict__ src,
                                       __half* __restrict__ dst, size_t j) {
    float4 v0 = ((const float4*)src)[j * 2];
    float4 v1 = ((const float4*)src)[j * 2 + 1];
    uint4 h;
    h.x = pack2h(v0.x, v0.y);
    h.y = pack2h(v0.z, v0.w);
    h.z = pack2h(v1.x, v1.y);
    h.w = pack2h(v1.z, v1.w);
    ((uint4*)dst)[j] = h;
}

// -------------------- router ------------------------------------------------
__global__ void router_kernel(const float* __restrict__ x,
                              const float* __restrict__ Wn,
                              const float* __restrict__ bn, int T) {
    int gw   = (blockIdx.x * blockDim.x + threadIdx.x) >> 5;
    int lane = threadIdx.x & 31;
    if (gw >= T) return;
    const float* xr = x + (size_t)gw * D_DIM;
    float acc[E_NUM];
#pragma unroll
    for (int e = 0; e < E_NUM; e++) acc[e] = 0.f;
    for (int d = lane; d < D_DIM; d += 32) {
        float xv = xr[d];
#pragma unroll
        for (int e = 0; e < E_NUM; e++) acc[e] += xv * Wn[d * E_NUM + e];
    }
#pragma unroll
    for (int off = 16; off; off >>= 1)
#pragma unroll
        for (int e = 0; e < E_NUM; e++)
            acc[e] += __shfl_xor_sync(0xffffffffu, acc[e], off);

    if (lane == 0) {
        float v[E_NUM];
#pragma unroll
        for (int e = 0; e < E_NUM; e++) v[e] = acc[e] + bn[e];
        int i0 = 0;
#pragma unroll
        for (int e = 1; e < E_NUM; e++) if (v[e] > v[i0]) i0 = e;
        int i1 = (i0 == 0) ? 1 : 0;
#pragma unroll
        for (int e = 0; e < E_NUM; e++)
            if (e != i0 && v[e] > v[i1]) i1 = e;
        float ex = expf(v[i1] - v[i0]);
        float g0 = 1.f / (1.f + ex);
        float g1 = ex / (1.f + ex);
        int p0 = atomicAdd(&g_ctrs[i0], 1);
        int p1 = atomicAdd(&g_ctrs[i1], 1);
        int b = gw * 2;
        g_topi[b] = i0; g_topi[b + 1] = i1;
        g_gate[b] = g0; g_gate[b + 1] = g1;
        g_pos[b]  = p0; g_pos[b + 1]  = p1;
    }
}

// -------------------- fused: build+gather (blocks [0,T*2)) + convert W1 ----
__global__ void gather_conv_kernel(const float* __restrict__ x,
                                   const float* __restrict__ W1,
                                   __half* __restrict__ w1h, int T2) {
    int b = blockIdx.x;
    if (b >= T2) {
        size_t j = (size_t)(b - T2) * 256 + threadIdx.x;  // uint4 index
        cvt_u4(W1, w1h, j);
        return;
    }
    __shared__ int s_slot;
    if (threadIdx.x == 0) {
        int e = g_topi[b];
        int base = 0;
#pragma unroll
        for (int j = 0; j < E_NUM; j++)
            if (j < e) base += g_ctrs[j];
        int slot = base + g_pos[b];
        g_rowtok[slot]  = b >> 1;
        g_rowgate[slot] = g_gate[b];
        s_slot = slot;
    }
    __syncthreads();
    int slot = s_slot;
    int tok  = b >> 1;
    int d    = threadIdx.x * 4;
    float4 v = *(const float4*)(x + (size_t)tok * D_DIM + d);
    uint2 h;
    h.x = pack2h(v.x, v.y);
    h.y = pack2h(v.z, v.w);
    ((uint2*)g_xh)[((size_t)slot * D_DIM + d) >> 2] = h;
}

// -------------------- GEMM core (device fn, both shapes) --------------------
#define A_OFF 0
#define B_OFF 16384
#define STAGE_BYTES 32768
#define NSTAGE 3
#define SMEM_DYN (NSTAGE * STAGE_BYTES)

template<int KDIM, int NDIM, bool RELU>
__device__ __forceinline__
void gemm_core(int e, int m0, int n0,
               const __half* __restrict__ Ah,
               const __half* __restrict__ Bh,
               const float* __restrict__ bias,
               __half* __restrict__ Ch,
               float* __restrict__ Cf) {
    const int cnt = g_ctrs[e];
    int base = 0;
#pragma unroll
    for (int j = 0; j < E_NUM; j++)
        if (j < e) base += g_ctrs[j];
    const int tid  = threadIdx.x;
    const int wid  = tid >> 5;
    const int lane = tid & 31;
    const int wm   = wid & 1;    // warp row (64 rows)
    const int wn   = wid >> 1;   // warp col (32 cols)

    extern __shared__ char smem[];
    const uint32_t sb = smem_u32(smem);

    const __half* Be = Bh + (size_t)e * KDIM * NDIM;

    // staging: 4 x 16B per operand per thread
    size_t a_go[4], b_go[4];
    uint32_t a_sw[4], b_sw[4];
#pragma unroll
    for (int i = 0; i < 4; i++) {
        int idx = tid + i * 256;
        int ar = idx >> 3, kg = idx & 7;
        int am = m0 + ar; if (am >= cnt) am = cnt - 1;
        a_go[i] = (size_t)(base + am) * KDIM + kg * 8;
        a_sw[i] = SW128(ar * 128 + kg * 16);
        int bh = idx >> 9, rem = idx & 511;
        int bk = rem >> 3, bn = rem & 7;
        b_go[i] = (size_t)bk * NDIM + n0 + bh * 64 + bn * 8;
        b_sw[i] = bh * 8192 + SW128(bk * 128 + bn * 16);
    }

    auto issue = [&](int c) {
        uint32_t st = sb + (c % NSTAGE) * STAGE_BYTES;
        const __half* pa = Ah + (size_t)c * 64;
        const __half* pb = Be + (size_t)c * 64 * NDIM;
#pragma unroll
        for (int i = 0; i < 4; i++) {
            CPASYNC16(st + A_OFF + a_sw[i], pa + a_go[i]);
            CPASYNC16(st + B_OFF + b_sw[i], pb + b_go[i]);
        }
        CPCOMMIT();
    };

    float C[4][4][4];
#pragma unroll
    for (int i = 0; i < 4; i++)
#pragma unroll
        for (int j = 0; j < 4; j++)
#pragma unroll
            for (int q = 0; q < 4; q++) C[i][j][q] = 0.f;

    constexpr int CHUNKS = KDIM / 64;
    const int g  = lane >> 3;
    const int lr = lane & 7;

    auto loadB = [&](uint32_t st, int ks, uint32_t (*bf)[4]) {
#pragma unroll
        for (int nt = 0; nt < 2; nt++) {
            int kk = ks * 16 + (g & 1) * 8 + lr;
            int nn = wn * 32 + nt * 16 + (g >> 1) * 8;
            int bhalf = nn >> 6;
            ldsm_x4_t(bf[nt], st + B_OFF + bhalf * 8192 +
                              SW128(kk * 128 + (nn & 63) * 2));
        }
    };

    issue(0); issue(1);
    for (int c = 0; c < CHUNKS; c++) {
        if (c + 1 < CHUNKS) CPWAIT1(); else CPWAIT0();
        __syncthreads();
        if (c + 2 < CHUNKS) issue(c + 2);
        uint32_t st = sb + (c % NSTAGE) * STAGE_BYTES;

        uint32_t bfr[2][2][4];
        loadB(st, 0, bfr[0]);
#pragma unroll
        for (int ks = 0; ks < 4; ks++) {
            if (ks < 3) loadB(st, ks + 1, bfr[(ks + 1) & 1]);
            uint32_t a[4][4];
#pragma unroll
            for (int mt = 0; mt < 4; mt++) {
                int row = wm * 64 + mt * 16 + (g & 1) * 8 + lr;
                int col = ks * 16 + (g >> 1) * 8;
                ldsm_x4(a[mt], st + A_OFF + SW128(row * 128 + col * 2));
            }
            uint32_t (*b)[4] = bfr[ks & 1];
#pragma unroll
            for (int mt = 0; mt < 4; mt++)
#pragma unroll
                for (int nt = 0; nt < 2; nt++)
#pragma unroll
                    for (int s = 0; s < 2; s++)
                        mma16816(C[mt][nt * 2 + s], a[mt],
                                 b[nt][s * 2], b[nt][s * 2 + 1]);
        }
    }

    // -------- epilogue
    const int qr = lane >> 2, qc = lane & 3;
    float bb0[4], bb1[4];
#pragma unroll
    for (int j = 0; j < 4; j++) {
        int col = n0 + wn * 32 + j * 8 + qc * 2;
        bb0[j] = bias[e * NDIM + col];
        bb1[j] = bias[e * NDIM + col + 1];
    }
#pragma unroll
    for (int mt = 0; mt < 4; mt++) {
#pragma unroll
        for (int j = 0; j < 4; j++) {
            int col = n0 + wn * 32 + j * 8 + qc * 2;
#pragma unroll
            for (int h = 0; h < 2; h++) {
                int lrow = wm * 64 + mt * 16 + qr + h * 8;
                if (m0 + lrow >= cnt) continue;
                int gr = base + m0 + lrow;
                float v0 = C[mt][j][h * 2 + 0] + bb0[j];
                float v1 = C[mt][j][h * 2 + 1] + bb1[j];
                if (RELU) {
                    v0 = v0 > 0.f ? v0 : 0.f;
                    v1 = v1 > 0.f ? v1 : 0.f;
                    ((uint32_t*)Ch)[((size_t)gr * NDIM + col) >> 1] = pack2h(v0, v1);
                } else {
                    int tok = g_rowtok[gr];
                    float gate = g_rowgate[gr];
                    float* op = Cf + (size_t)tok * NDIM + col;
                    atomicAdd(op,     gate * v0);   // exactly 2 commutative
                    atomicAdd(op + 1, gate * v1);   // fp32 adds per element
                }
            }
        }
    }
}

// -------------------- MEGA kernel: convW2 || GEMM1 || GEMM2 -----------------
// z=0: convert W2 (32x16=512 CTAs), bump g_ctrs[16].
// z=1..8: GEMM1 expert z-1; on finish bump g_ctrs[8+e].
// z=9..16: GEMM2 expert z-9; spin for w2 ready + gemm1 done[e].
__global__ __launch_bounds__(256, 2)
void mega_kernel(const __half* __restrict__ xh,
                 const float* __restrict__ b1,
                 const float* __restrict__ b2,
                 float* __restrict__ out,
                 const float* __restrict__ W2) {
    const int z = blockIdx.z;
    if (z == 0) {
        size_t cta = (size_t)blockIdx.y * gridDim.x + blockIdx.x;  // 0..511
        size_t basej = cta * 8192 + threadIdx.x;
#pragma unroll
        for (int it = 0; it < 32; it++)
            cvt_u4(W2, g_w2h, basej + (size_t)it * 256);
        __threadfence();
        __syncthreads();
        if (threadIdx.x == 0) atomicAdd(&g_ctrs[16], 1);
        return;
    }
    if (z <= E_NUM) {
        // ---- GEMM1: x @ W1_e, relu -> g_hh
        const int e  = z - 1;
        const int m0 = blockIdx.y * 128;
        if (m0 >= g_ctrs[e]) return;
        const int n0 = blockIdx.x * 128;
        gemm_core<D_DIM, F_DIM, true>(e, m0, n0, g_xh, g_w1h, b1, g_hh, nullptr);
        __threadfence();
        __syncthreads();
        if (threadIdx.x == 0) atomicAdd(&g_ctrs[8 + e], 1);
        return;
    }
    // ---- GEMM2: h @ W2_e, +b2, *gate, atomic into out
    const int e    = z - E_NUM - 1;
    const int flat = blockIdx.y * gridDim.x + blockIdx.x;   // 0..511
    const int cnt  = g_ctrs[e];
    const int m0   = (flat >> 3) * 128;
    const int n0   = (flat & 7) * 128;
    if (m0 >= cnt) return;
    const int target = (F_DIM / 128) * ((cnt + 127) >> 7);  // active GEMM1 CTAs
    if (threadIdx.x == 0) {
        while (atomicAdd(&g_ctrs[16], 0) < 512) __nanosleep(256);
        while (atomicAdd(&g_ctrs[8 + e], 0) < target) __nanosleep(256);
    }
    __syncthreads();
    gemm_core<F_DIM, D_DIM, false>(e, m0, n0, g_hh, g_w2h, b2, nullptr, out);
}

// -------------------- launch ------------------------------------------------
extern "C" void kernel_launch(void* const* d_in, const int* in_sizes, int n_in,
                              void* d_out, int out_size) {
    const float* x  = (const float*)d_in[0];
    const float* Wn = (const float*)d_in[1];
    const float* bn = (const float*)d_in[2];
    const float* W1 = (const float*)d_in[3];
    const float* b1 = (const float*)d_in[4];
    const float* W2 = (const float*)d_in[5];
    const float* b2 = (const float*)d_in[6];
    const int T = in_sizes[0] / D_DIM;

    cudaFuncSetAttribute(mega_kernel,
                         cudaFuncAttributeMaxDynamicSharedMemorySize, SMEM_DYN);

    __half *w1h, *xh;
    int* ctrptr;
    cudaGetSymbolAddress((void**)&w1h, g_w1h);
    cudaGetSymbolAddress((void**)&xh, g_xh);
    cudaGetSymbolAddress((void**)&ctrptr, g_ctrs);

    // memset nodes: zero counters and output accumulator
    cudaMemsetAsync(ctrptr, 0, 32 * sizeof(int), 0);
    cudaMemsetAsync(d_out, 0, (size_t)out_size * sizeof(float), 0);

    // kernel 1: router
    router_kernel<<<(T * 32 + 255) / 256, 256>>>(x, Wn, bn, T);

    // kernel 2: fused build+gather || convert W1
    const int NCONV1 = (int)((size_t)E_NUM * D_DIM * F_DIM / 8 / 256); // 16384
    gather_conv_kernel<<<T * 2 + NCONV1, 256>>>(x, W1, w1h, T * 2);

    // kernel 3: MEGA — convert W2 (z=0) || GEMM1 (z=1..8) || GEMM2 (z=9..16)
    dim3 gm(F_DIM / 128, (MAXT + 127) / 128, 1 + 2 * E_NUM);
    mega_kernel<<<gm, 256, SMEM_DYN>>>(xh, b1, b2, (float*)d_out, W2);
}

// round 15
// speedup vs baseline: 1.1148x; 1.1148x over previous
#include <cuda_runtime.h>
#include <cuda_fp16.h>
#include <math.h>
#include <stdint.h>

// SparseMoE: T=2048, D=1024, F=4096, E=8, top-2.
// memset(cnt,out) -> router (smem-transposed Wn, float4) ->
// [build+gather || convert W1] -> [GEMM1 (fp16 mma.sync, relu) || convert W2]
// -> GEMM2 (atomic out, +b2, *gate).
// GEMM: 128x128 tile, 256 thr (8 warps, 2x4, 64x32/warp), 3-stage ring,
// 2 CTAs/SM, ks-level B-fragment double buffering.

#define D_DIM 1024
#define E_NUM 8
#define F_DIM 4096
#define MAXT  2048
#define MAXROWS (2 * MAXT)

// -------------------- device scratch (no cudaMalloc allowed) ---------------
__device__ __half g_w1h[(size_t)E_NUM * D_DIM * F_DIM];
__device__ __half g_w2h[(size_t)E_NUM * F_DIM * D_DIM];
__device__ __half g_xh[(size_t)MAXROWS * D_DIM];
__device__ __half g_hh[(size_t)MAXROWS * F_DIM];
__device__ int   g_cnt[E_NUM];
__device__ int   g_topi[MAXT * 2];
__device__ float g_gate[MAXT * 2];
__device__ int   g_pos[MAXT * 2];
__device__ int   g_rowtok[MAXROWS];
__device__ float g_rowgate[MAXROWS];

// -------------------- helpers ----------------------------------------------
__device__ __forceinline__ uint32_t smem_u32(const void* p) {
    uint32_t a;
    asm("{ .reg .u64 t; cvta.to.shared.u64 t, %1; cvt.u32.u64 %0, t; }"
        : "=r"(a) : "l"(p));
    return a;
}

#define SW128(o) ((uint32_t)(o) ^ ((((uint32_t)(o)) >> 3) & 0x70u))

#define CPASYNC16(s, g) \
    asm volatile("cp.async.cg.shared.global [%0], [%1], 16;" \
        :: "r"((uint32_t)(s)), "l"(g) : "memory")
#define CPCOMMIT() asm volatile("cp.async.commit_group;" ::: "memory")
#define CPWAIT1()  asm volatile("cp.async.wait_group 1;" ::: "memory")
#define CPWAIT0()  asm volatile("cp.async.wait_group 0;" ::: "memory")

__device__ __forceinline__ void ldsm_x4(uint32_t* r, uint32_t addr) {
    asm volatile("ldmatrix.sync.aligned.m8n8.x4.shared.b16 {%0,%1,%2,%3}, [%4];"
        : "=r"(r[0]), "=r"(r[1]), "=r"(r[2]), "=r"(r[3]) : "r"(addr));
}
__device__ __forceinline__ void ldsm_x4_t(uint32_t* r, uint32_t addr) {
    asm volatile("ldmatrix.sync.aligned.m8n8.x4.trans.shared.b16 {%0,%1,%2,%3}, [%4];"
        : "=r"(r[0]), "=r"(r[1]), "=r"(r[2]), "=r"(r[3]) : "r"(addr));
}
__device__ __forceinline__ void mma16816(float* c, const uint32_t* a,
                                         uint32_t b0, uint32_t b1) {
    asm volatile(
        "mma.sync.aligned.m16n8k16.row.col.f32.f16.f16.f32 "
        "{%0,%1,%2,%3}, {%4,%5,%6,%7}, {%8,%9}, {%0,%1,%2,%3};"
        : "+f"(c[0]), "+f"(c[1]), "+f"(c[2]), "+f"(c[3])
        : "r"(a[0]), "r"(a[1]), "r"(a[2]), "r"(a[3]), "r"(b0), "r"(b1));
}

__device__ __forceinline__ uint32_t pack2h(float a, float b) {
    __half2 h = __floats2half2_rn(a, b);
    return *(uint32_t*)&h;
}

__device__ __forceinline__ void cvt_u4(const float* __restrict__ src,
                                       __half* __restrict__ dst, size_t j) {
    float4 v0 = ((const float4*)src)[j * 2];
    float4 v1 = ((const float4*)src)[j * 2 + 1];
    uint4 h;
    h.x = pack2h(v0.x, v0.y);
    h.y = pack2h(v0.z, v0.w);
    h.z = pack2h(v1.x, v1.y);
    h.w = pack2h(v1.z, v1.w);
    ((uint4*)dst)[j] = h;
}

// -------------------- router (smem-transposed Wn, float4 both sides) --------
__global__ __launch_bounds__(256)
void router_kernel(const float* __restrict__ x,
                   const float* __restrict__ Wn,
                   const float* __restrict__ bn, int T) {
    __shared__ float WnT[E_NUM][D_DIM];   // 32 KB, transposed gate weights
    const int tid  = threadIdx.x;
    const int wid  = tid >> 5;
    const int lane = tid & 31;

    for (int i = tid; i < D_DIM * E_NUM; i += 256) {
        int d = i >> 3, e = i & 7;
        WnT[e][d] = Wn[i];
    }
    __syncthreads();

    int tok = blockIdx.x * 8 + wid;
    if (tok >= T) return;
    const float4* xr = (const float4*)(x + (size_t)tok * D_DIM);

    float acc[E_NUM];
#pragma unroll
    for (int e = 0; e < E_NUM; e++) acc[e] = 0.f;

#pragma unroll
    for (int it = 0; it < D_DIM / 128; it++) {          // 8 iterations
        int d4 = it * 32 + lane;                        // float4 index
        float4 xv = xr[d4];
#pragma unroll
        for (int e = 0; e < E_NUM; e++) {
            float4 wv = *(const float4*)&WnT[e][d4 * 4];
            acc[e] += xv.x * wv.x + xv.y * wv.y + xv.z * wv.z + xv.w * wv.w;
        }
    }
#pragma unroll
    for (int off = 16; off; off >>= 1)
#pragma unroll
        for (int e = 0; e < E_NUM; e++)
            acc[e] += __shfl_xor_sync(0xffffffffu, acc[e], off);

    if (lane == 0) {
        float v[E_NUM];
#pragma unroll
        for (int e = 0; e < E_NUM; e++) v[e] = acc[e] + bn[e];
        int i0 = 0;
#pragma unroll
        for (int e = 1; e < E_NUM; e++) if (v[e] > v[i0]) i0 = e;
        int i1 = (i0 == 0) ? 1 : 0;
#pragma unroll
        for (int e = 0; e < E_NUM; e++)
            if (e != i0 && v[e] > v[i1]) i1 = e;
        float ex = expf(v[i1] - v[i0]);
        float g0 = 1.f / (1.f + ex);
        float g1 = ex / (1.f + ex);
        int p0 = atomicAdd(&g_cnt[i0], 1);
        int p1 = atomicAdd(&g_cnt[i1], 1);
        int b = tok * 2;
        g_topi[b] = i0; g_topi[b + 1] = i1;
        g_gate[b] = g0; g_gate[b + 1] = g1;
        g_pos[b]  = p0; g_pos[b + 1]  = p1;
    }
}

// -------------------- fused: build+gather (blocks [0,T*2)) + convert W1 ----
__global__ void gather_conv_kernel(const float* __restrict__ x,
                                   const float* __restrict__ W1,
                                   __half* __restrict__ w1h, int T2) {
    int b = blockIdx.x;
    if (b >= T2) {
        size_t j = (size_t)(b - T2) * 256 + threadIdx.x;  // uint4 index
        cvt_u4(W1, w1h, j);
        return;
    }
    __shared__ int s_slot;
    if (threadIdx.x == 0) {
        int e = g_topi[b];
        int base = 0;
#pragma unroll
        for (int j = 0; j < E_NUM; j++)
            if (j < e) base += g_cnt[j];
        int slot = base + g_pos[b];
        g_rowtok[slot]  = b >> 1;
        g_rowgate[slot] = g_gate[b];
        s_slot = slot;
    }
    __syncthreads();
    int slot = s_slot;
    int tok  = b >> 1;
    int d    = threadIdx.x * 4;
    float4 v = *(const float4*)(x + (size_t)tok * D_DIM + d);
    uint2 h;
    h.x = pack2h(v.x, v.y);
    h.y = pack2h(v.z, v.w);
    ((uint2*)g_xh)[((size_t)slot * D_DIM + d) >> 2] = h;
}

// -------------------- grouped GEMM (fp16 mma.sync, f32 accum) ---------------
// FUSECONV: z==0 slice converts W2 (csrc->cdst) instead of GEMM work.
// RELU=true: writes fp16 h. RELU=false: atomicAdd gate*(acc+bias) into Cf[tok].
#define A_OFF 0
#define B_OFF 16384
#define STAGE_BYTES 32768
#define NSTAGE 3
#define SMEM_DYN (NSTAGE * STAGE_BYTES)

template<int KDIM, int NDIM, bool RELU, bool FUSECONV>
__global__ __launch_bounds__(256, 2)
void moe_gemm_kernel(const __half* __restrict__ Ah,
                     const __half* __restrict__ Bh,
                     const float* __restrict__ bias,
                     __half* __restrict__ Ch,
                     float* __restrict__ Cf,
                     const float* __restrict__ csrc,
                     __half* __restrict__ cdst) {
    int zz = blockIdx.z;
    if (FUSECONV) {
        if (zz == 0) {
            // convert W2: 512 CTAs x 256 thr x 32 uint4 = 33.55M halfs
            size_t cta = (size_t)blockIdx.y * gridDim.x + blockIdx.x;
            size_t base = cta * 8192 + threadIdx.x;   // uint4 index
#pragma unroll
            for (int it = 0; it < 32; it++)
                cvt_u4(csrc, cdst, base + (size_t)it * 256);
            return;
        }
        zz -= 1;
    }
    const int e   = zz;
    const int cnt = g_cnt[e];
    const int m0  = blockIdx.y * 128;
    if (m0 >= cnt) return;
    int base = 0;
#pragma unroll
    for (int j = 0; j < E_NUM; j++)
        if (j < e) base += g_cnt[j];
    const int n0   = blockIdx.x * 128;
    const int tid  = threadIdx.x;
    const int wid  = tid >> 5;
    const int lane = tid & 31;
    const int wm   = wid & 1;    // warp row (64 rows)
    const int wn   = wid >> 1;   // warp col (32 cols)

    extern __shared__ char smem[];
    const uint32_t sb = smem_u32(smem);

    const __half* Be = Bh + (size_t)e * KDIM * NDIM;

    // staging: 4 x 16B per operand per thread (256 thr covers 16KB each)
    size_t a_go[4], b_go[4];
    uint32_t a_sw[4], b_sw[4];
#pragma unroll
    for (int i = 0; i < 4; i++) {
        int idx = tid + i * 256;
        int ar = idx >> 3, kg = idx & 7;           // A: 128 rows x 8 x 16B
        int am = m0 + ar; if (am >= cnt) am = cnt - 1;
        a_go[i] = (size_t)(base + am) * KDIM + kg * 8;
        a_sw[i] = SW128(ar * 128 + kg * 16);
        int bh = idx >> 9, rem = idx & 511;        // B: 2 halves x 64k x 8 x 16B
        int bk = rem >> 3, bn = rem & 7;
        b_go[i] = (size_t)bk * NDIM + n0 + bh * 64 + bn * 8;
        b_sw[i] = bh * 8192 + SW128(bk * 128 + bn * 16);
    }

    auto issue = [&](int c) {
        uint32_t st = sb + (c % NSTAGE) * STAGE_BYTES;
        const __half* pa = Ah + (size_t)c * 64;
        const __half* pb = Be + (size_t)c * 64 * NDIM;
#pragma unroll
        for (int i = 0; i < 4; i++) {
            CPASYNC16(st + A_OFF + a_sw[i], pa + a_go[i]);
            CPASYNC16(st + B_OFF + b_sw[i], pb + b_go[i]);
        }
        CPCOMMIT();
    };

    float C[4][4][4];    // [mt 16rows][n8 frag][quad]
#pragma unroll
    for (int i = 0; i < 4; i++)
#pragma unroll
        for (int j = 0; j < 4; j++)
#pragma unroll
            for (int q = 0; q < 4; q++) C[i][j][q] = 0.f;

    constexpr int CHUNKS = KDIM / 64;
    const int g  = lane >> 3;       // ldmatrix lane group
    const int lr = lane & 7;

    auto loadB = [&](uint32_t st, int ks, uint32_t (*bf)[4]) {
#pragma unroll
        for (int nt = 0; nt < 2; nt++) {
            int kk = ks * 16 + (g & 1) * 8 + lr;
            int nn = wn * 32 + nt * 16 + (g >> 1) * 8;
            int bhalf = nn >> 6;
            ldsm_x4_t(bf[nt], st + B_OFF + bhalf * 8192 +
                              SW128(kk * 128 + (nn & 63) * 2));
        }
    };

    issue(0); issue(1);
    for (int c = 0; c < CHUNKS; c++) {
        if (c + 1 < CHUNKS) CPWAIT1(); else CPWAIT0();
        __syncthreads();            // stage c ready; stage (c-1)%3 readers done
        if (c + 2 < CHUNKS) issue(c + 2);
        uint32_t st = sb + (c % NSTAGE) * STAGE_BYTES;

        uint32_t bfr[2][2][4];      // [parity][nt][frag]
        loadB(st, 0, bfr[0]);
#pragma unroll
        for (int ks = 0; ks < 4; ks++) {
            if (ks < 3) loadB(st, ks + 1, bfr[(ks + 1) & 1]);
            uint32_t a[4][4];
#pragma unroll
            for (int mt = 0; mt < 4; mt++) {
                int row = wm * 64 + mt * 16 + (g & 1) * 8 + lr;
                int col = ks * 16 + (g >> 1) * 8;
                ldsm_x4(a[mt], st + A_OFF + SW128(row * 128 + col * 2));
            }
            uint32_t (*b)[4] = bfr[ks & 1];
#pragma unroll
            for (int mt = 0; mt < 4; mt++)
#pragma unroll
                for (int nt = 0; nt < 2; nt++)
#pragma unroll
                    for (int s = 0; s < 2; s++)
                        mma16816(C[mt][nt * 2 + s], a[mt],
                                 b[nt][s * 2], b[nt][s * 2 + 1]);
        }
    }

    // -------- epilogue
    const int qr = lane >> 2, qc = lane & 3;
    float bb0[4], bb1[4];
#pragma unroll
    for (int j = 0; j < 4; j++) {
        int col = n0 + wn * 32 + j * 8 + qc * 2;
        bb0[j] = bias[e * NDIM + col];
        bb1[j] = bias[e * NDIM + col + 1];
    }
#pragma unroll
    for (int mt = 0; mt < 4; mt++) {
#pragma unroll
        for (int j = 0; j < 4; j++) {
            int col = n0 + wn * 32 + j * 8 + qc * 2;
#pragma unroll
            for (int h = 0; h < 2; h++) {
                int lrow = wm * 64 + mt * 16 + qr + h * 8;
                if (m0 + lrow >= cnt) continue;
                int gr = base + m0 + lrow;
                float v0 = C[mt][j][h * 2 + 0] + bb0[j];
                float v1 = C[mt][j][h * 2 + 1] + bb1[j];
                if (RELU) {
                    v0 = v0 > 0.f ? v0 : 0.f;
                    v1 = v1 > 0.f ? v1 : 0.f;
                    ((uint32_t*)Ch)[((size_t)gr * NDIM + col) >> 1] = pack2h(v0, v1);
                } else {
                    int tok = g_rowtok[gr];
                    float gate = g_rowgate[gr];
                    float* op = Cf + (size_t)tok * NDIM + col;
                    atomicAdd(op,     gate * v0);   // exactly 2 commutative
                    atomicAdd(op + 1, gate * v1);   // fp32 adds per element
                }
            }
        }
    }
}

// -------------------- launch ------------------------------------------------
extern "C" void kernel_launch(void* const* d_in, const int* in_sizes, int n_in,
                              void* d_out, int out_size) {
    const float* x  = (const float*)d_in[0];
    const float* Wn = (const float*)d_in[1];
    const float* bn = (const float*)d_in[2];
    const float* W1 = (const float*)d_in[3];
    const float* b1 = (const float*)d_in[4];
    const float* W2 = (const float*)d_in[5];
    const float* b2 = (const float*)d_in[6];
    const int T = in_sizes[0] / D_DIM;

    cudaFuncSetAttribute(moe_gemm_kernel<D_DIM, F_DIM, true, true>,
                         cudaFuncAttributeMaxDynamicSharedMemorySize, SMEM_DYN);
    cudaFuncSetAttribute(moe_gemm_kernel<F_DIM, D_DIM, false, false>,
                         cudaFuncAttributeMaxDynamicSharedMemorySize, SMEM_DYN);

    __half *w1h, *w2h, *xh, *hh;
    int* cntptr;
    cudaGetSymbolAddress((void**)&w1h, g_w1h);
    cudaGetSymbolAddress((void**)&w2h, g_w2h);
    cudaGetSymbolAddress((void**)&xh, g_xh);
    cudaGetSymbolAddress((void**)&hh, g_hh);
    cudaGetSymbolAddress((void**)&cntptr, g_cnt);

    // memset nodes: zero expert counters and output accumulator
    cudaMemsetAsync(cntptr, 0, E_NUM * sizeof(int), 0);
    cudaMemsetAsync(d_out, 0, (size_t)out_size * sizeof(float), 0);

    // kernel 1: router (8 tokens per 256-thr block)
    router_kernel<<<(T + 7) / 8, 256>>>(x, Wn, bn, T);

    // kernel 2: fused build+gather (needs router) || convert W1
    const int NCONV1 = (int)((size_t)E_NUM * D_DIM * F_DIM / 8 / 256); // 16384
    gather_conv_kernel<<<T * 2 + NCONV1, 256>>>(x, W1, w1h, T * 2);

    // kernel 3: GEMM1 (z=1..8) || convert W2 (z=0)
    const int MT = (MAXT + 127) / 128;
    dim3 g1(F_DIM / 128, MT, E_NUM + 1);
    moe_gemm_kernel<D_DIM, F_DIM, true, true><<<g1, 256, SMEM_DYN>>>(
        xh, w1h, b1, hh, nullptr, W2, w2h);

    // kernel 4: GEMM2 (atomic accumulate into d_out)
    dim3 g2(D_DIM / 128, MT, E_NUM);
    moe_gemm_kernel<F_DIM, D_DIM, false, false><<<g2, 256, SMEM_DYN>>>(
        hh, w2h, b2, nullptr, (float*)d_out, nullptr, nullptr);
}

// round 16
// speedup vs baseline: 1.1370x; 1.0199x over previous
#include <cuda_runtime.h>
#include <cuda_fp16.h>
#include <math.h>
#include <stdint.h>

// SparseMoE: T=2048, D=1024, F=4096, E=8, top-2.
// memset(cnt,out) -> [router || convert W1] -> gather ->
// [GEMM1 (fp16 mma.sync, relu) || convert W2] -> GEMM2 (atomic out, +b2, *gate).
// GEMM: 128x128 tile, 256 thr (8 warps, 2x4, 64x32/warp), 3-stage ring,
// 2 CTAs/SM, ks-level B-fragment double buffering.

#define D_DIM 1024
#define E_NUM 8
#define F_DIM 4096
#define MAXT  2048
#define MAXROWS (2 * MAXT)
#define NCONV1 2048   // convert-W1 role CTAs fused into the router launch

// -------------------- device scratch (no cudaMalloc allowed) ---------------
__device__ __half g_w1h[(size_t)E_NUM * D_DIM * F_DIM];
__device__ __half g_w2h[(size_t)E_NUM * F_DIM * D_DIM];
__device__ __half g_xh[(size_t)MAXROWS * D_DIM];
__device__ __half g_hh[(size_t)MAXROWS * F_DIM];
__device__ int   g_cnt[E_NUM];
__device__ int   g_topi[MAXT * 2];
__device__ float g_gate[MAXT * 2];
__device__ int   g_pos[MAXT * 2];
__device__ int   g_rowtok[MAXROWS];
__device__ float g_rowgate[MAXROWS];

// -------------------- helpers ----------------------------------------------
__device__ __forceinline__ uint32_t smem_u32(const void* p) {
    uint32_t a;
    asm("{ .reg .u64 t; cvta.to.shared.u64 t, %1; cvt.u32.u64 %0, t; }"
        : "=r"(a) : "l"(p));
    return a;
}

#define SW128(o) ((uint32_t)(o) ^ ((((uint32_t)(o)) >> 3) & 0x70u))

#define CPASYNC16(s, g) \
    asm volatile("cp.async.cg.shared.global [%0], [%1], 16;" \
        :: "r"((uint32_t)(s)), "l"(g) : "memory")
#define CPCOMMIT() asm volatile("cp.async.commit_group;" ::: "memory")
#define CPWAIT1()  asm volatile("cp.async.wait_group 1;" ::: "memory")
#define CPWAIT0()  asm volatile("cp.async.wait_group 0;" ::: "memory")

__device__ __forceinline__ void ldsm_x4(uint32_t* r, uint32_t addr) {
    asm volatile("ldmatrix.sync.aligned.m8n8.x4.shared.b16 {%0,%1,%2,%3}, [%4];"
        : "=r"(r[0]), "=r"(r[1]), "=r"(r[2]), "=r"(r[3]) : "r"(addr));
}
__device__ __forceinline__ void ldsm_x4_t(uint32_t* r, uint32_t addr) {
    asm volatile("ldmatrix.sync.aligned.m8n8.x4.trans.shared.b16 {%0,%1,%2,%3}, [%4];"
        : "=r"(r[0]), "=r"(r[1]), "=r"(r[2]), "=r"(r[3]) : "r"(addr));
}
__device__ __forceinline__ void mma16816(float* c, const uint32_t* a,
                                         uint32_t b0, uint32_t b1) {
    asm volatile(
        "mma.sync.aligned.m16n8k16.row.col.f32.f16.f16.f32 "
        "{%0,%1,%2,%3}, {%4,%5,%6,%7}, {%8,%9}, {%0,%1,%2,%3};"
        : "+f"(c[0]), "+f"(c[1]), "+f"(c[2]), "+f"(c[3])
        : "r"(a[0]), "r"(a[1]), "r"(a[2]), "r"(a[3]), "r"(b0), "r"(b1));
}

__device__ __forceinline__ uint32_t pack2h(float a, float b) {
    __half2 h = __floats2half2_rn(a, b);
    return *(uint32_t*)&h;
}

__device__ __forceinline__ void cvt_u4(const float* __restrict__ src,
                                       __half* __restrict__ dst, size_t j) {
    float4 v0 = ((const float4*)src)[j * 2];
    float4 v1 = ((const float4*)src)[j * 2 + 1];
    uint4 h;
    h.x = pack2h(v0.x, v0.y);
    h.y = pack2h(v0.z, v0.w);
    h.z = pack2h(v1.x, v1.y);
    h.w = pack2h(v1.z, v1.w);
    ((uint4*)dst)[j] = h;
}

// -------------------- kernel 1: router || convert W1 ------------------------
// blocks [0,256): router (8 tokens per 256-thr block, smem-transposed Wn).
// blocks [256, 256+NCONV1): convert W1, 8 strided uint4 per thread.
__global__ __launch_bounds__(256)
void router_conv_kernel(const float* __restrict__ x,
                        const float* __restrict__ Wn,
                        const float* __restrict__ bn,
                        const float* __restrict__ W1,
                        __half* __restrict__ w1h, int T) {
    __shared__ float WnT[E_NUM][D_DIM];   // 32 KB (router role only)
    const int blk = blockIdx.x;
    if (blk >= 256) {
        // ---- convert W1 role: 2048 CTAs x 256 thr x 8 uint4
        size_t basej = (size_t)(blk - 256) * 2048 + threadIdx.x;
#pragma unroll
        for (int it = 0; it < 8; it++)
            cvt_u4(W1, w1h, basej + (size_t)it * 256);
        return;
    }

    const int tid  = threadIdx.x;
    const int wid  = tid >> 5;
    const int lane = tid & 31;

    for (int i = tid; i < D_DIM * E_NUM; i += 256) {
        int d = i >> 3, e = i & 7;
        WnT[e][d] = Wn[i];
    }
    __syncthreads();

    int tok = blk * 8 + wid;
    if (tok >= T) return;
    const float4* xr = (const float4*)(x + (size_t)tok * D_DIM);

    float acc[E_NUM];
#pragma unroll
    for (int e = 0; e < E_NUM; e++) acc[e] = 0.f;

#pragma unroll
    for (int it = 0; it < D_DIM / 128; it++) {          // 8 iterations
        int d4 = it * 32 + lane;                        // float4 index
        float4 xv = xr[d4];
#pragma unroll
        for (int e = 0; e < E_NUM; e++) {
            float4 wv = *(const float4*)&WnT[e][d4 * 4];
            acc[e] += xv.x * wv.x + xv.y * wv.y + xv.z * wv.z + xv.w * wv.w;
        }
    }
#pragma unroll
    for (int off = 16; off; off >>= 1)
#pragma unroll
        for (int e = 0; e < E_NUM; e++)
            acc[e] += __shfl_xor_sync(0xffffffffu, acc[e], off);

    if (lane == 0) {
        float v[E_NUM];
#pragma unroll
        for (int e = 0; e < E_NUM; e++) v[e] = acc[e] + bn[e];
        int i0 = 0;
#pragma unroll
        for (int e = 1; e < E_NUM; e++) if (v[e] > v[i0]) i0 = e;
        int i1 = (i0 == 0) ? 1 : 0;
#pragma unroll
        for (int e = 0; e < E_NUM; e++)
            if (e != i0 && v[e] > v[i1]) i1 = e;
        float ex = expf(v[i1] - v[i0]);
        float g0 = 1.f / (1.f + ex);
        float g1 = ex / (1.f + ex);
        int p0 = atomicAdd(&g_cnt[i0], 1);
        int p1 = atomicAdd(&g_cnt[i1], 1);
        int b = tok * 2;
        g_topi[b] = i0; g_topi[b + 1] = i1;
        g_gate[b] = g0; g_gate[b + 1] = g1;
        g_pos[b]  = p0; g_pos[b + 1]  = p1;
    }
}

// -------------------- kernel 2: build + gather -------------------------------
__global__ void gather_kernel(const float* __restrict__ x) {
    int b = blockIdx.x;
    __shared__ int s_slot;
    if (threadIdx.x == 0) {
        int e = g_topi[b];
        int base = 0;
#pragma unroll
        for (int j = 0; j < E_NUM; j++)
            if (j < e) base += g_cnt[j];
        int slot = base + g_pos[b];
        g_rowtok[slot]  = b >> 1;
        g_rowgate[slot] = g_gate[b];
        s_slot = slot;
    }
    __syncthreads();
    int slot = s_slot;
    int tok  = b >> 1;
    int d    = threadIdx.x * 4;
    float4 v = *(const float4*)(x + (size_t)tok * D_DIM + d);
    uint2 h;
    h.x = pack2h(v.x, v.y);
    h.y = pack2h(v.z, v.w);
    ((uint2*)g_xh)[((size_t)slot * D_DIM + d) >> 2] = h;
}

// -------------------- grouped GEMM (fp16 mma.sync, f32 accum) ---------------
// FUSECONV: z==0 slice converts W2 (csrc->cdst) instead of GEMM work.
// RELU=true: writes fp16 h. RELU=false: atomicAdd gate*(acc+bias) into Cf[tok].
#define A_OFF 0
#define B_OFF 16384
#define STAGE_BYTES 32768
#define NSTAGE 3
#define SMEM_DYN (NSTAGE * STAGE_BYTES)

template<int KDIM, int NDIM, bool RELU, bool FUSECONV>
__global__ __launch_bounds__(256, 2)
void moe_gemm_kernel(const __half* __restrict__ Ah,
                     const __half* __restrict__ Bh,
                     const float* __restrict__ bias,
                     __half* __restrict__ Ch,
                     float* __restrict__ Cf,
                     const float* __restrict__ csrc,
                     __half* __restrict__ cdst) {
    int zz = blockIdx.z;
    if (FUSECONV) {
        if (zz == 0) {
            // convert W2: 512 CTAs x 256 thr x 32 uint4 = 33.55M halfs
            size_t cta = (size_t)blockIdx.y * gridDim.x + blockIdx.x;
            size_t base = cta * 8192 + threadIdx.x;   // uint4 index
#pragma unroll
            for (int it = 0; it < 32; it++)
                cvt_u4(csrc, cdst, base + (size_t)it * 256);
            return;
        }
        zz -= 1;
    }
    const int e   = zz;
    const int cnt = g_cnt[e];
    const int m0  = blockIdx.y * 128;
    if (m0 >= cnt) return;
    int base = 0;
#pragma unroll
    for (int j = 0; j < E_NUM; j++)
        if (j < e) base += g_cnt[j];
    const int n0   = blockIdx.x * 128;
    const int tid  = threadIdx.x;
    const int wid  = tid >> 5;
    const int lane = tid & 31;
    const int wm   = wid & 1;    // warp row (64 rows)
    const int wn   = wid >> 1;   // warp col (32 cols)

    extern __shared__ char smem[];
    const uint32_t sb = smem_u32(smem);

    const __half* Be = Bh + (size_t)e * KDIM * NDIM;

    // staging: 4 x 16B per operand per thread (256 thr covers 16KB each)
    size_t a_go[4], b_go[4];
    uint32_t a_sw[4], b_sw[4];
#pragma unroll
    for (int i = 0; i < 4; i++) {
        int idx = tid + i * 256;
        int ar = idx >> 3, kg = idx & 7;           // A: 128 rows x 8 x 16B
        int am = m0 + ar; if (am >= cnt) am = cnt - 1;
        a_go[i] = (size_t)(base + am) * KDIM + kg * 8;
        a_sw[i] = SW128(ar * 128 + kg * 16);
        int bh = idx >> 9, rem = idx & 511;        // B: 2 halves x 64k x 8 x 16B
        int bk = rem >> 3, bn = rem & 7;
        b_go[i] = (size_t)bk * NDIM + n0 + bh * 64 + bn * 8;
        b_sw[i] = bh * 8192 + SW128(bk * 128 + bn * 16);
    }

    auto issue = [&](int c) {
        uint32_t st = sb + (c % NSTAGE) * STAGE_BYTES;
        const __half* pa = Ah + (size_t)c * 64;
        const __half* pb = Be + (size_t)c * 64 * NDIM;
#pragma unroll
        for (int i = 0; i < 4; i++) {
            CPASYNC16(st + A_OFF + a_sw[i], pa + a_go[i]);
            CPASYNC16(st + B_OFF + b_sw[i], pb + b_go[i]);
        }
        CPCOMMIT();
    };

    float C[4][4][4];    // [mt 16rows][n8 frag][quad]
#pragma unroll
    for (int i = 0; i < 4; i++)
#pragma unroll
        for (int j = 0; j < 4; j++)
#pragma unroll
            for (int q = 0; q < 4; q++) C[i][j][q] = 0.f;

    constexpr int CHUNKS = KDIM / 64;
    const int g  = lane >> 3;       // ldmatrix lane group
    const int lr = lane & 7;

    auto loadB = [&](uint32_t st, int ks, uint32_t (*bf)[4]) {
#pragma unroll
        for (int nt = 0; nt < 2; nt++) {
            int kk = ks * 16 + (g & 1) * 8 + lr;
            int nn = wn * 32 + nt * 16 + (g >> 1) * 8;
            int bhalf = nn >> 6;
            ldsm_x4_t(bf[nt], st + B_OFF + bhalf * 8192 +
                              SW128(kk * 128 + (nn & 63) * 2));
        }
    };

    issue(0); issue(1);
    for (int c = 0; c < CHUNKS; c++) {
        if (c + 1 < CHUNKS) CPWAIT1(); else CPWAIT0();
        __syncthreads();            // stage c ready; stage (c-1)%3 readers done
        if (c + 2 < CHUNKS) issue(c + 2);
        uint32_t st = sb + (c % NSTAGE) * STAGE_BYTES;

        uint32_t bfr[2][2][4];      // [parity][nt][frag]
        loadB(st, 0, bfr[0]);
#pragma unroll
        for (int ks = 0; ks < 4; ks++) {
            if (ks < 3) loadB(st, ks + 1, bfr[(ks + 1) & 1]);
            uint32_t a[4][4];
#pragma unroll
            for (int mt = 0; mt < 4; mt++) {
                int row = wm * 64 + mt * 16 + (g & 1) * 8 + lr;
                int col = ks * 16 + (g >> 1) * 8;
                ldsm_x4(a[mt], st + A_OFF + SW128(row * 128 + col * 2));
            }
            uint32_t (*b)[4] = bfr[ks & 1];
#pragma unroll
            for (int mt = 0; mt < 4; mt++)
#pragma unroll
                for (int nt = 0; nt < 2; nt++)
#pragma unroll
                    for (int s = 0; s < 2; s++)
                        mma16816(C[mt][nt * 2 + s], a[mt],
                                 b[nt][s * 2], b[nt][s * 2 + 1]);
        }
    }

    // -------- epilogue
    const int qr = lane >> 2, qc = lane & 3;
    float bb0[4], bb1[4];
#pragma unroll
    for (int j = 0; j < 4; j++) {
        int col = n0 + wn * 32 + j * 8 + qc * 2;
        bb0[j] = bias[e * NDIM + col];
        bb1[j] = bias[e * NDIM + col + 1];
    }
#pragma unroll
    for (int mt = 0; mt < 4; mt++) {
#pragma unroll
        for (int j = 0; j < 4; j++) {
            int col = n0 + wn * 32 + j * 8 + qc * 2;
#pragma unroll
            for (int h = 0; h < 2; h++) {
                int lrow = wm * 64 + mt * 16 + qr + h * 8;
                if (m0 + lrow >= cnt) continue;
                int gr = base + m0 + lrow;
                float v0 = C[mt][j][h * 2 + 0] + bb0[j];
                float v1 = C[mt][j][h * 2 + 1] + bb1[j];
                if (RELU) {
                    v0 = v0 > 0.f ? v0 : 0.f;
                    v1 = v1 > 0.f ? v1 : 0.f;
                    ((uint32_t*)Ch)[((size_t)gr * NDIM + col) >> 1] = pack2h(v0, v1);
                } else {
                    int tok = g_rowtok[gr];
                    float gate = g_rowgate[gr];
                    float* op = Cf + (size_t)tok * NDIM + col;
                    atomicAdd(op,     gate * v0);   // exactly 2 commutative
                    atomicAdd(op + 1, gate * v1);   // fp32 adds per element
                }
            }
        }
    }
}

// -------------------- launch ------------------------------------------------
extern "C" void kernel_launch(void* const* d_in, const int* in_sizes, int n_in,
                              void* d_out, int out_size) {
    const float* x  = (const float*)d_in[0];
    const float* Wn = (const float*)d_in[1];
    const float* bn = (const float*)d_in[2];
    const float* W1 = (const float*)d_in[3];
    const float* b1 = (const float*)d_in[4];
    const float* W2 = (const float*)d_in[5];
    const float* b2 = (const float*)d_in[6];
    const int T = in_sizes[0] / D_DIM;

    cudaFuncSetAttribute(moe_gemm_kernel<D_DIM, F_DIM, true, true>,
                         cudaFuncAttributeMaxDynamicSharedMemorySize, SMEM_DYN);
    cudaFuncSetAttribute(moe_gemm_kernel<F_DIM, D_DIM, false, false>,
                         cudaFuncAttributeMaxDynamicSharedMemorySize, SMEM_DYN);

    __half *w1h, *w2h, *xh, *hh;
    int* cntptr;
    cudaGetSymbolAddress((void**)&w1h, g_w1h);
    cudaGetSymbolAddress((void**)&w2h, g_w2h);
    cudaGetSymbolAddress((void**)&xh, g_xh);
    cudaGetSymbolAddress((void**)&hh, g_hh);
    cudaGetSymbolAddress((void**)&cntptr, g_cnt);

    // memset nodes: zero expert counters and output accumulator
    cudaMemsetAsync(cntptr, 0, E_NUM * sizeof(int), 0);
    cudaMemsetAsync(d_out, 0, (size_t)out_size * sizeof(float), 0);

    // kernel 1: router (blocks 0..255) || convert W1 (blocks 256..)
    router_conv_kernel<<<256 + NCONV1, 256>>>(x, Wn, bn, W1, w1h, T);

    // kernel 2: build + gather (needs router)
    gather_kernel<<<T * 2, 256>>>(x);

    // kernel 3: GEMM1 (z=1..8) || convert W2 (z=0)
    const int MT = (MAXT + 127) / 128;
    dim3 g1(F_DIM / 128, MT, E_NUM + 1);
    moe_gemm_kernel<D_DIM, F_DIM, true, true><<<g1, 256, SMEM_DYN>>>(
        xh, w1h, b1, hh, nullptr, W2, w2h);

    // kernel 4: GEMM2 (atomic accumulate into d_out)
    dim3 g2(D_DIM / 128, MT, E_NUM);
    moe_gemm_kernel<F_DIM, D_DIM, false, false><<<g2, 256, SMEM_DYN>>>(
        hh, w2h, b2, nullptr, (float*)d_out, nullptr, nullptr);
}

// round 17
// speedup vs baseline: 1.1454x; 1.0073x over previous
#include <cuda_runtime.h>
#include <cuda_fp16.h>
#include <math.h>
#include <stdint.h>

// SparseMoE: T=2048, D=1024, F=4096, E=8, top-2.
// memset(cnt,out) -> [router || convert W1] -> gather (warp-per-assignment) ->
// [GEMM1 (fp16 mma.sync, relu) || convert W2] -> GEMM2 (atomic out, +b2, *gate).
// GEMM: 128x128 tile, 256 thr (8 warps, 2x4, 64x32/warp), 3-stage ring,
// 2 CTAs/SM, ks-level B-fragment double buffering.

#define D_DIM 1024
#define E_NUM 8
#define F_DIM 4096
#define MAXT  2048
#define MAXROWS (2 * MAXT)
#define NCONV1 2048   // convert-W1 role CTAs fused into the router launch

// -------------------- device scratch (no cudaMalloc allowed) ---------------
__device__ __half g_w1h[(size_t)E_NUM * D_DIM * F_DIM];
__device__ __half g_w2h[(size_t)E_NUM * F_DIM * D_DIM];
__device__ __half g_xh[(size_t)MAXROWS * D_DIM];
__device__ __half g_hh[(size_t)MAXROWS * F_DIM];
__device__ int   g_cnt[E_NUM];
__device__ int   g_topi[MAXT * 2];
__device__ float g_gate[MAXT * 2];
__device__ int   g_pos[MAXT * 2];
__device__ int   g_rowtok[MAXROWS];
__device__ float g_rowgate[MAXROWS];

// -------------------- helpers ----------------------------------------------
__device__ __forceinline__ uint32_t smem_u32(const void* p) {
    uint32_t a;
    asm("{ .reg .u64 t; cvta.to.shared.u64 t, %1; cvt.u32.u64 %0, t; }"
        : "=r"(a) : "l"(p));
    return a;
}

#define SW128(o) ((uint32_t)(o) ^ ((((uint32_t)(o)) >> 3) & 0x70u))

#define CPASYNC16(s, g) \
    asm volatile("cp.async.cg.shared.global [%0], [%1], 16;" \
        :: "r"((uint32_t)(s)), "l"(g) : "memory")
#define CPCOMMIT() asm volatile("cp.async.commit_group;" ::: "memory")
#define CPWAIT1()  asm volatile("cp.async.wait_group 1;" ::: "memory")
#define CPWAIT0()  asm volatile("cp.async.wait_group 0;" ::: "memory")

__device__ __forceinline__ void ldsm_x4(uint32_t* r, uint32_t addr) {
    asm volatile("ldmatrix.sync.aligned.m8n8.x4.shared.b16 {%0,%1,%2,%3}, [%4];"
        : "=r"(r[0]), "=r"(r[1]), "=r"(r[2]), "=r"(r[3]) : "r"(addr));
}
__device__ __forceinline__ void ldsm_x4_t(uint32_t* r, uint32_t addr) {
    asm volatile("ldmatrix.sync.aligned.m8n8.x4.trans.shared.b16 {%0,%1,%2,%3}, [%4];"
        : "=r"(r[0]), "=r"(r[1]), "=r"(r[2]), "=r"(r[3]) : "r"(addr));
}
__device__ __forceinline__ void mma16816(float* c, const uint32_t* a,
                                         uint32_t b0, uint32_t b1) {
    asm volatile(
        "mma.sync.aligned.m16n8k16.row.col.f32.f16.f16.f32 "
        "{%0,%1,%2,%3}, {%4,%5,%6,%7}, {%8,%9}, {%0,%1,%2,%3};"
        : "+f"(c[0]), "+f"(c[1]), "+f"(c[2]), "+f"(c[3])
        : "r"(a[0]), "r"(a[1]), "r"(a[2]), "r"(a[3]), "r"(b0), "r"(b1));
}

__device__ __forceinline__ uint32_t pack2h(float a, float b) {
    __half2 h = __floats2half2_rn(a, b);
    return *(uint32_t*)&h;
}

__device__ __forceinline__ void cvt_u4(const float* __restrict__ src,
                                       __half* __restrict__ dst, size_t j) {
    float4 v0 = ((const float4*)src)[j * 2];
    float4 v1 = ((const float4*)src)[j * 2 + 1];
    uint4 h;
    h.x = pack2h(v0.x, v0.y);
    h.y = pack2h(v0.z, v0.w);
    h.z = pack2h(v1.x, v1.y);
    h.w = pack2h(v1.z, v1.w);
    ((uint4*)dst)[j] = h;
}

// -------------------- kernel 1: router || convert W1 ------------------------
// blocks [0,256): router (8 tokens per 256-thr block, smem-transposed Wn).
// blocks [256, 256+NCONV1): convert W1, 8 strided uint4 per thread.
__global__ __launch_bounds__(256)
void router_conv_kernel(const float* __restrict__ x,
                        const float* __restrict__ Wn,
                        const float* __restrict__ bn,
                        const float* __restrict__ W1,
                        __half* __restrict__ w1h, int T) {
    __shared__ float WnT[E_NUM][D_DIM];   // 32 KB (router role only)
    const int blk = blockIdx.x;
    if (blk >= 256) {
        // ---- convert W1 role: 2048 CTAs x 256 thr x 8 uint4
        size_t basej = (size_t)(blk - 256) * 2048 + threadIdx.x;
#pragma unroll
        for (int it = 0; it < 8; it++)
            cvt_u4(W1, w1h, basej + (size_t)it * 256);
        return;
    }

    const int tid  = threadIdx.x;
    const int wid  = tid >> 5;
    const int lane = tid & 31;

    for (int i = tid; i < D_DIM * E_NUM; i += 256) {
        int d = i >> 3, e = i & 7;
        WnT[e][d] = Wn[i];
    }
    __syncthreads();

    int tok = blk * 8 + wid;
    if (tok >= T) return;
    const float4* xr = (const float4*)(x + (size_t)tok * D_DIM);

    float acc[E_NUM];
#pragma unroll
    for (int e = 0; e < E_NUM; e++) acc[e] = 0.f;

#pragma unroll
    for (int it = 0; it < D_DIM / 128; it++) {          // 8 iterations
        int d4 = it * 32 + lane;                        // float4 index
        float4 xv = xr[d4];
#pragma unroll
        for (int e = 0; e < E_NUM; e++) {
            float4 wv = *(const float4*)&WnT[e][d4 * 4];
            acc[e] += xv.x * wv.x + xv.y * wv.y + xv.z * wv.z + xv.w * wv.w;
        }
    }
#pragma unroll
    for (int off = 16; off; off >>= 1)
#pragma unroll
        for (int e = 0; e < E_NUM; e++)
            acc[e] += __shfl_xor_sync(0xffffffffu, acc[e], off);

    if (lane == 0) {
        float v[E_NUM];
#pragma unroll
        for (int e = 0; e < E_NUM; e++) v[e] = acc[e] + bn[e];
        int i0 = 0;
#pragma unroll
        for (int e = 1; e < E_NUM; e++) if (v[e] > v[i0]) i0 = e;
        int i1 = (i0 == 0) ? 1 : 0;
#pragma unroll
        for (int e = 0; e < E_NUM; e++)
            if (e != i0 && v[e] > v[i1]) i1 = e;
        float ex = expf(v[i1] - v[i0]);
        float g0 = 1.f / (1.f + ex);
        float g1 = ex / (1.f + ex);
        int p0 = atomicAdd(&g_cnt[i0], 1);
        int p1 = atomicAdd(&g_cnt[i1], 1);
        int b = tok * 2;
        g_topi[b] = i0; g_topi[b + 1] = i1;
        g_gate[b] = g0; g_gate[b + 1] = g1;
        g_pos[b]  = p0; g_pos[b + 1]  = p1;
    }
}

// -------------------- kernel 2: build + gather (warp per assignment) --------
// 8 warps/CTA; warp w handles assignment blk*8 + w. Lane 0 computes the slot
// and broadcasts via shfl — no smem, no block barrier.
__global__ __launch_bounds__(256)
void gather_kernel(const float* __restrict__ x, int T2) {
    const int wid  = threadIdx.x >> 5;
    const int lane = threadIdx.x & 31;
    const int b    = blockIdx.x * 8 + wid;
    if (b >= T2) return;

    int slot;
    if (lane == 0) {
        int e = g_topi[b];
        int base = 0;
#pragma unroll
        for (int j = 0; j < E_NUM; j++)
            if (j < e) base += g_cnt[j];
        slot = base + g_pos[b];
        g_rowtok[slot]  = b >> 1;
        g_rowgate[slot] = g_gate[b];
    }
    slot = __shfl_sync(0xffffffffu, slot, 0);

    const int tok = b >> 1;
    const float4* xr = (const float4*)(x + (size_t)tok * D_DIM);
    uint2* dst = (uint2*)(g_xh + (size_t)slot * D_DIM);
#pragma unroll
    for (int it = 0; it < 8; it++) {          // 32 float4s per warp per iter
        int d4 = it * 32 + lane;
        float4 v = xr[d4];
        uint2 h;
        h.x = pack2h(v.x, v.y);
        h.y = pack2h(v.z, v.w);
        dst[d4] = h;
    }
}

// -------------------- grouped GEMM (fp16 mma.sync, f32 accum) ---------------
// FUSECONV: z==0 slice converts W2 (csrc->cdst) instead of GEMM work.
// RELU=true: writes fp16 h. RELU=false: atomicAdd gate*(acc+bias) into Cf[tok].
#define A_OFF 0
#define B_OFF 16384
#define STAGE_BYTES 32768
#define NSTAGE 3
#define SMEM_DYN (NSTAGE * STAGE_BYTES)

template<int KDIM, int NDIM, bool RELU, bool FUSECONV>
__global__ __launch_bounds__(256, 2)
void moe_gemm_kernel(const __half* __restrict__ Ah,
                     const __half* __restrict__ Bh,
                     const float* __restrict__ bias,
                     __half* __restrict__ Ch,
                     float* __restrict__ Cf,
                     const float* __restrict__ csrc,
                     __half* __restrict__ cdst) {
    int zz = blockIdx.z;
    if (FUSECONV) {
        if (zz == 0) {
            // convert W2: 512 CTAs x 256 thr x 32 uint4 = 33.55M halfs
            size_t cta = (size_t)blockIdx.y * gridDim.x + blockIdx.x;
            size_t base = cta * 8192 + threadIdx.x;   // uint4 index
#pragma unroll
            for (int it = 0; it < 32; it++)
                cvt_u4(csrc, cdst, base + (size_t)it * 256);
            return;
        }
        zz -= 1;
    }
    const int e   = zz;
    const int cnt = g_cnt[e];
    const int m0  = blockIdx.y * 128;
    if (m0 >= cnt) return;
    int base = 0;
#pragma unroll
    for (int j = 0; j < E_NUM; j++)
        if (j < e) base += g_cnt[j];
    const int n0   = blockIdx.x * 128;
    const int tid  = threadIdx.x;
    const int wid  = tid >> 5;
    const int lane = tid & 31;
    const int wm   = wid & 1;    // warp row (64 rows)
    const int wn   = wid >> 1;   // warp col (32 cols)

    extern __shared__ char smem[];
    const uint32_t sb = smem_u32(smem);

    const __half* Be = Bh + (size_t)e * KDIM * NDIM;

    // staging: 4 x 16B per operand per thread (256 thr covers 16KB each)
    size_t a_go[4], b_go[4];
    uint32_t a_sw[4], b_sw[4];
#pragma unroll
    for (int i = 0; i < 4; i++) {
        int idx = tid + i * 256;
        int ar = idx >> 3, kg = idx & 7;           // A: 128 rows x 8 x 16B
        int am = m0 + ar; if (am >= cnt) am = cnt - 1;
        a_go[i] = (size_t)(base + am) * KDIM + kg * 8;
        a_sw[i] = SW128(ar * 128 + kg * 16);
        int bh = idx >> 9, rem = idx & 511;        // B: 2 halves x 64k x 8 x 16B
        int bk = rem >> 3, bn = rem & 7;
        b_go[i] = (size_t)bk * NDIM + n0 + bh * 64 + bn * 8;
        b_sw[i] = bh * 8192 + SW128(bk * 128 + bn * 16);
    }

    auto issue = [&](int c) {
        uint32_t st = sb + (c % NSTAGE) * STAGE_BYTES;
        const __half* pa = Ah + (size_t)c * 64;
        const __half* pb = Be + (size_t)c * 64 * NDIM;
#pragma unroll
        for (int i = 0; i < 4; i++) {
            CPASYNC16(st + A_OFF + a_sw[i], pa + a_go[i]);
            CPASYNC16(st + B_OFF + b_sw[i], pb + b_go[i]);
        }
        CPCOMMIT();
    };

    float C[4][4][4];    // [mt 16rows][n8 frag][quad]
#pragma unroll
    for (int i = 0; i < 4; i++)
#pragma unroll
        for (int j = 0; j < 4; j++)
#pragma unroll
            for (int q = 0; q < 4; q++) C[i][j][q] = 0.f;

    constexpr int CHUNKS = KDIM / 64;
    const int g  = lane >> 3;       // ldmatrix lane group
    const int lr = lane & 7;

    auto loadB = [&](uint32_t st, int ks, uint32_t (*bf)[4]) {
#pragma unroll
        for (int nt = 0; nt < 2; nt++) {
            int kk = ks * 16 + (g & 1) * 8 + lr;
            int nn = wn * 32 + nt * 16 + (g >> 1) * 8;
            int bhalf = nn >> 6;
            ldsm_x4_t(bf[nt], st + B_OFF + bhalf * 8192 +
                              SW128(kk * 128 + (nn & 63) * 2));
        }
    };

    issue(0); issue(1);
    for (int c = 0; c < CHUNKS; c++) {
        if (c + 1 < CHUNKS) CPWAIT1(); else CPWAIT0();
        __syncthreads();            // stage c ready; stage (c-1)%3 readers done
        if (c + 2 < CHUNKS) issue(c + 2);
        uint32_t st = sb + (c % NSTAGE) * STAGE_BYTES;

        uint32_t bfr[2][2][4];      // [parity][nt][frag]
        loadB(st, 0, bfr[0]);
#pragma unroll
        for (int ks = 0; ks < 4; ks++) {
            if (ks < 3) loadB(st, ks + 1, bfr[(ks + 1) & 1]);
            uint32_t a[4][4];
#pragma unroll
            for (int mt = 0; mt < 4; mt++) {
                int row = wm * 64 + mt * 16 + (g & 1) * 8 + lr;
                int col = ks * 16 + (g >> 1) * 8;
                ldsm_x4(a[mt], st + A_OFF + SW128(row * 128 + col * 2));
            }
            uint32_t (*b)[4] = bfr[ks & 1];
#pragma unroll
            for (int mt = 0; mt < 4; mt++)
#pragma unroll
                for (int nt = 0; nt < 2; nt++)
#pragma unroll
                    for (int s = 0; s < 2; s++)
                        mma16816(C[mt][nt * 2 + s], a[mt],
                                 b[nt][s * 2], b[nt][s * 2 + 1]);
        }
    }

    // -------- epilogue
    const int qr = lane >> 2, qc = lane & 3;
    float bb0[4], bb1[4];
#pragma unroll
    for (int j = 0; j < 4; j++) {
        int col = n0 + wn * 32 + j * 8 + qc * 2;
        bb0[j] = bias[e * NDIM + col];
        bb1[j] = bias[e * NDIM + col + 1];
    }
#pragma unroll
    for (int mt = 0; mt < 4; mt++) {
#pragma unroll
        for (int j = 0; j < 4; j++) {
            int col = n0 + wn * 32 + j * 8 + qc * 2;
#pragma unroll
            for (int h = 0; h < 2; h++) {
                int lrow = wm * 64 + mt * 16 + qr + h * 8;
                if (m0 + lrow >= cnt) continue;
                int gr = base + m0 + lrow;
                float v0 = C[mt][j][h * 2 + 0] + bb0[j];
                float v1 = C[mt][j][h * 2 + 1] + bb1[j];
                if (RELU) {
                    v0 = v0 > 0.f ? v0 : 0.f;
                    v1 = v1 > 0.f ? v1 : 0.f;
                    ((uint32_t*)Ch)[((size_t)gr * NDIM + col) >> 1] = pack2h(v0, v1);
                } else {
                    int tok = g_rowtok[gr];
                    float gate = g_rowgate[gr];
                    float* op = Cf + (size_t)tok * NDIM + col;
                    atomicAdd(op,     gate * v0);   // exactly 2 commutative
                    atomicAdd(op + 1, gate * v1);   // fp32 adds per element
                }
            }
        }
    }
}

// -------------------- launch ------------------------------------------------
extern "C" void kernel_launch(void* const* d_in, const int* in_sizes, int n_in,
                              void* d_out, int out_size) {
    const float* x  = (const float*)d_in[0];
    const float* Wn = (const float*)d_in[1];
    const float* bn = (const float*)d_in[2];
    const float* W1 = (const float*)d_in[3];
    const float* b1 = (const float*)d_in[4];
    const float* W2 = (const float*)d_in[5];
    const float* b2 = (const float*)d_in[6];
    const int T = in_sizes[0] / D_DIM;

    cudaFuncSetAttribute(moe_gemm_kernel<D_DIM, F_DIM, true, true>,
                         cudaFuncAttributeMaxDynamicSharedMemorySize, SMEM_DYN);
    cudaFuncSetAttribute(moe_gemm_kernel<F_DIM, D_DIM, false, false>,
                         cudaFuncAttributeMaxDynamicSharedMemorySize, SMEM_DYN);

    __half *w1h, *w2h, *xh, *hh;
    int* cntptr;
    cudaGetSymbolAddress((void**)&w1h, g_w1h);
    cudaGetSymbolAddress((void**)&w2h, g_w2h);
    cudaGetSymbolAddress((void**)&xh, g_xh);
    cudaGetSymbolAddress((void**)&hh, g_hh);
    cudaGetSymbolAddress((void**)&cntptr, g_cnt);

    // memset nodes: zero expert counters and output accumulator
    cudaMemsetAsync(cntptr, 0, E_NUM * sizeof(int), 0);
    cudaMemsetAsync(d_out, 0, (size_t)out_size * sizeof(float), 0);

    // kernel 1: router (blocks 0..255) || convert W1 (blocks 256..)
    router_conv_kernel<<<256 + NCONV1, 256>>>(x, Wn, bn, W1, w1h, T);

    // kernel 2: build + gather (warp per assignment, 8 per CTA)
    gather_kernel<<<(T * 2 + 7) / 8, 256>>>(x, T * 2);

    // kernel 3: GEMM1 (z=1..8) || convert W2 (z=0)
    const int MT = (MAXT + 127) / 128;
    dim3 g1(F_DIM / 128, MT, E_NUM + 1);
    moe_gemm_kernel<D_DIM, F_DIM, true, true><<<g1, 256, SMEM_DYN>>>(
        xh, w1h, b1, hh, nullptr, W2, w2h);

    // kernel 4: GEMM2 (atomic accumulate into d_out)
    dim3 g2(D_DIM / 128, MT, E_NUM);
    moe_gemm_kernel<F_DIM, D_DIM, false, false><<<g2, 256, SMEM_DYN>>>(
        hh, w2h, b2, nullptr, (float*)d_out, nullptr, nullptr);
}